// round 5
// baseline (speedup 1.0000x reference)
#include <cuda_runtime.h>
#include <cstdint>

// Problem constants
#define BSZ     4
#define SEQ     2048
#define DIMSZ   512
#define HEADS   8
#define HD      64
#define M_TOT   (BSZ * SEQ)   // 8192

// Scratch (device globals: allocation rules forbid cudaMalloc)
__device__ float g_Q[M_TOT * DIMSZ];
__device__ float g_K[M_TOT * DIMSZ];
__device__ float g_V[M_TOT * DIMSZ];
__device__ float g_A[M_TOT * DIMSZ];

// ---------------------------------------------------------------------------
// GEMM:  D[M,512] = A[M,512] * W[512,512]^T   (both K-major, fp32)
// 128x128 CTA tile, BK=8, 256 threads, 8x8 microtile, float4 smem reads.
// ---------------------------------------------------------------------------
__global__ __launch_bounds__(256, 2)
void gemm_nt(const float* __restrict__ A, const float* __restrict__ W,
             float* __restrict__ D)
{
    __shared__ float As[8][128];
    __shared__ float Ws[8][128];

    const int tid = threadIdx.x;
    const int tx  = tid & 15;
    const int ty  = tid >> 4;
    const int rowBase = blockIdx.y * 128;
    const int colBase = blockIdx.x * 128;

    // load mapping: each thread fetches one float4 of A and one of W per k-tile
    const int lr = tid >> 1;          // 0..127
    const int lk = (tid & 1) * 4;     // 0 or 4

    const float* Aptr = A + (size_t)(rowBase + lr) * DIMSZ + lk;
    const float* Wptr = W + (size_t)(colBase + lr) * DIMSZ + lk;

    float acc[8][8];
#pragma unroll
    for (int i = 0; i < 8; i++)
#pragma unroll
        for (int j = 0; j < 8; j++) acc[i][j] = 0.f;

    for (int k0 = 0; k0 < DIMSZ; k0 += 8) {
        float4 av = *(const float4*)(Aptr + k0);
        float4 wv = *(const float4*)(Wptr + k0);
        __syncthreads();
        As[lk + 0][lr] = av.x; As[lk + 1][lr] = av.y;
        As[lk + 2][lr] = av.z; As[lk + 3][lr] = av.w;
        Ws[lk + 0][lr] = wv.x; Ws[lk + 1][lr] = wv.y;
        Ws[lk + 2][lr] = wv.z; Ws[lk + 3][lr] = wv.w;
        __syncthreads();
#pragma unroll
        for (int kk = 0; kk < 8; kk++) {
            float4 a0 = *(const float4*)&As[kk][ty * 4];
            float4 a1 = *(const float4*)&As[kk][ty * 4 + 64];
            float4 b0 = *(const float4*)&Ws[kk][tx * 4];
            float4 b1 = *(const float4*)&Ws[kk][tx * 4 + 64];
            float a[8] = {a0.x, a0.y, a0.z, a0.w, a1.x, a1.y, a1.z, a1.w};
            float b[8] = {b0.x, b0.y, b0.z, b0.w, b1.x, b1.y, b1.z, b1.w};
#pragma unroll
            for (int i = 0; i < 8; i++)
#pragma unroll
                for (int j = 0; j < 8; j++)
                    acc[i][j] += a[i] * b[j];
        }
    }

#pragma unroll
    for (int i = 0; i < 8; i++) {
        int r = rowBase + ty * 4 + (i < 4 ? i : 60 + i);   // i>=4 -> 64+(i-4)
        float4 o0 = make_float4(acc[i][0], acc[i][1], acc[i][2], acc[i][3]);
        float4 o1 = make_float4(acc[i][4], acc[i][5], acc[i][6], acc[i][7]);
        *(float4*)&D[(size_t)r * DIMSZ + colBase + tx * 4]      = o0;
        *(float4*)&D[(size_t)r * DIMSZ + colBase + tx * 4 + 64] = o1;
    }
}

// ---------------------------------------------------------------------------
// Fused flash-attention (fp32, online softmax).
// CTA: 128 query rows of one (b,h); key/value tiles of 64.
// Thread microtile: 8 rows x 4 cols; shuffle reductions over 16-lane groups.
// ---------------------------------------------------------------------------
#define QS_LD 132   // [64][132]  Qs[d][row]
#define KS_LD 68    // [64][68]   Ks[d][key]
#define VS_LD 64    // [64][64]   Vs[key][dim]
#define PS_LD 132   // [64][132]  Ps[key][row]
#define ATTN_SMEM ((64*QS_LD + 64*KS_LD + 64*VS_LD + 64*PS_LD) * 4)

__global__ __launch_bounds__(256, 2)
void attn_kernel(const float* __restrict__ Q, const float* __restrict__ K,
                 const float* __restrict__ V, const int* __restrict__ mask,
                 float* __restrict__ Aout)
{
    extern __shared__ float sm[];
    float* Qs = sm;
    float* Ks = Qs + 64 * QS_LD;
    float* Vs = Ks + 64 * KS_LD;
    float* Ps = Vs + 64 * VS_LD;

    const int tid = threadIdx.x;
    const int tx  = tid & 15;
    const int ty  = tid >> 4;
    const int b   = blockIdx.z;
    const int h   = blockIdx.y;
    const int qb  = blockIdx.x * 128;

    const float* Qb = Q + ((size_t)b * SEQ) * DIMSZ + h * HD;
    const float* Kb = K + ((size_t)b * SEQ) * DIMSZ + h * HD;
    const float* Vb = V + ((size_t)b * SEQ) * DIMSZ + h * HD;
    const int*   mb = mask + b * SEQ;

    // Load Q tile transposed: Qs[d][r], r in [0,128), d in [0,64)
    for (int i = tid; i < 128 * 16; i += 256) {
        int r  = i >> 4;
        int d4 = (i & 15) * 4;
        float4 v = *(const float4*)&Qb[(size_t)(qb + r) * DIMSZ + d4];
        Qs[(d4 + 0) * QS_LD + r] = v.x;
        Qs[(d4 + 1) * QS_LD + r] = v.y;
        Qs[(d4 + 2) * QS_LD + r] = v.z;
        Qs[(d4 + 3) * QS_LD + r] = v.w;
    }

    float Ob[8][4];
    float mrun[8], lrun[8];
#pragma unroll
    for (int i = 0; i < 8; i++) {
        mrun[i] = -1e30f;
        lrun[i] = 0.f;
#pragma unroll
        for (int c = 0; c < 4; c++) Ob[i][c] = 0.f;
    }

    for (int k0 = 0; k0 < SEQ; k0 += 64) {
        __syncthreads();   // previous AV done before overwriting Ks/Vs
        // Load K (transposed) and V (natural) tiles
        for (int i = tid; i < 64 * 16; i += 256) {
            int kr = i >> 4;
            int d4 = (i & 15) * 4;
            float4 kv = *(const float4*)&Kb[(size_t)(k0 + kr) * DIMSZ + d4];
            Ks[(d4 + 0) * KS_LD + kr] = kv.x;
            Ks[(d4 + 1) * KS_LD + kr] = kv.y;
            Ks[(d4 + 2) * KS_LD + kr] = kv.z;
            Ks[(d4 + 3) * KS_LD + kr] = kv.w;
            float4 vv = *(const float4*)&Vb[(size_t)(k0 + kr) * DIMSZ + d4];
            *(float4*)&Vs[kr * VS_LD + d4] = vv;
        }
        __syncthreads();

        // S = Q * K^T  (8 rows x 4 key-cols per thread)
        float S[8][4];
#pragma unroll
        for (int i = 0; i < 8; i++)
#pragma unroll
            for (int j = 0; j < 4; j++) S[i][j] = 0.f;

#pragma unroll 4
        for (int d = 0; d < 64; d++) {
            float4 a0 = *(const float4*)&Qs[d * QS_LD + ty * 4];
            float4 a1 = *(const float4*)&Qs[d * QS_LD + ty * 4 + 64];
            float4 b0 = *(const float4*)&Ks[d * KS_LD + tx * 4];
            float a[8] = {a0.x, a0.y, a0.z, a0.w, a1.x, a1.y, a1.z, a1.w};
            float bb[4] = {b0.x, b0.y, b0.z, b0.w};
#pragma unroll
            for (int i = 0; i < 8; i++)
#pragma unroll
                for (int j = 0; j < 4; j++)
                    S[i][j] += a[i] * bb[j];
        }

        // mask + scale (masked score is exactly -1e6, matching reference)
        int mk[4];
#pragma unroll
        for (int j = 0; j < 4; j++) mk[j] = __ldg(&mb[k0 + tx * 4 + j]);
#pragma unroll
        for (int i = 0; i < 8; i++)
#pragma unroll
            for (int j = 0; j < 4; j++)
                S[i][j] = mk[j] ? S[i][j] * 0.125f : -1.0e6f;

        // online softmax
#pragma unroll
        for (int i = 0; i < 8; i++) {
            float mx = fmaxf(fmaxf(S[i][0], S[i][1]), fmaxf(S[i][2], S[i][3]));
            mx = fmaxf(mx, __shfl_xor_sync(0xffffffffu, mx, 8, 16));
            mx = fmaxf(mx, __shfl_xor_sync(0xffffffffu, mx, 4, 16));
            mx = fmaxf(mx, __shfl_xor_sync(0xffffffffu, mx, 2, 16));
            mx = fmaxf(mx, __shfl_xor_sync(0xffffffffu, mx, 1, 16));
            float mnew = fmaxf(mrun[i], mx);
            float corr = __expf(mrun[i] - mnew);
            float p0 = __expf(S[i][0] - mnew);
            float p1 = __expf(S[i][1] - mnew);
            float p2 = __expf(S[i][2] - mnew);
            float p3 = __expf(S[i][3] - mnew);
            float rs = (p0 + p1) + (p2 + p3);
            rs += __shfl_xor_sync(0xffffffffu, rs, 8, 16);
            rs += __shfl_xor_sync(0xffffffffu, rs, 4, 16);
            rs += __shfl_xor_sync(0xffffffffu, rs, 2, 16);
            rs += __shfl_xor_sync(0xffffffffu, rs, 1, 16);
            lrun[i] = lrun[i] * corr + rs;
            mrun[i] = mnew;
#pragma unroll
            for (int c = 0; c < 4; c++) Ob[i][c] *= corr;
            int row = ty * 4 + (i < 4 ? i : 60 + i);
            Ps[(tx * 4 + 0) * PS_LD + row] = p0;
            Ps[(tx * 4 + 1) * PS_LD + row] = p1;
            Ps[(tx * 4 + 2) * PS_LD + row] = p2;
            Ps[(tx * 4 + 3) * PS_LD + row] = p3;
        }
        __syncthreads();

        // O += P * V
#pragma unroll 4
        for (int k = 0; k < 64; k++) {
            float4 a0 = *(const float4*)&Ps[k * PS_LD + ty * 4];
            float4 a1 = *(const float4*)&Ps[k * PS_LD + ty * 4 + 64];
            float4 v0 = *(const float4*)&Vs[k * VS_LD + tx * 4];
            float a[8] = {a0.x, a0.y, a0.z, a0.w, a1.x, a1.y, a1.z, a1.w};
            float vv[4] = {v0.x, v0.y, v0.z, v0.w};
#pragma unroll
            for (int i = 0; i < 8; i++)
#pragma unroll
                for (int c = 0; c < 4; c++)
                    Ob[i][c] += a[i] * vv[c];
        }
    }

    // epilogue: normalize and write back (head-interleaved layout = transpose-merge)
#pragma unroll
    for (int i = 0; i < 8; i++) {
        int row = qb + ty * 4 + (i < 4 ? i : 60 + i);
        float inv = 1.0f / lrun[i];
        float4 o = make_float4(Ob[i][0] * inv, Ob[i][1] * inv,
                               Ob[i][2] * inv, Ob[i][3] * inv);
        *(float4*)&Aout[((size_t)b * SEQ + row) * DIMSZ + h * HD + tx * 4] = o;
    }
}

// ---------------------------------------------------------------------------
extern "C" void kernel_launch(void* const* d_in, const int* in_sizes, int n_in,
                              void* d_out, int out_size)
{
    (void)in_sizes; (void)n_in; (void)out_size;
    const float* x    = (const float*)d_in[0];
    const float* Wq   = (const float*)d_in[1];
    const float* Wk   = (const float*)d_in[2];
    const float* Wv   = (const float*)d_in[3];
    const float* Wo   = (const float*)d_in[4];
    const int*   mask = (const int*)d_in[5];
    float*       out  = (float*)d_out;

    float *Qp = nullptr, *Kp = nullptr, *Vp = nullptr, *Ap = nullptr;
    cudaGetSymbolAddress((void**)&Qp, g_Q);
    cudaGetSymbolAddress((void**)&Kp, g_K);
    cudaGetSymbolAddress((void**)&Vp, g_V);
    cudaGetSymbolAddress((void**)&Ap, g_A);

    dim3 ggrid(DIMSZ / 128, M_TOT / 128);   // (4, 64)
    gemm_nt<<<ggrid, 256>>>(x, Wq, Qp);
    gemm_nt<<<ggrid, 256>>>(x, Wk, Kp);
    gemm_nt<<<ggrid, 256>>>(x, Wv, Vp);

    cudaFuncSetAttribute(attn_kernel,
                         cudaFuncAttributeMaxDynamicSharedMemorySize,
                         ATTN_SMEM);
    attn_kernel<<<dim3(SEQ / 128, HEADS, BSZ), 256, ATTN_SMEM>>>(Qp, Kp, Vp, mask, Ap);

    gemm_nt<<<ggrid, 256>>>(Ap, Wo, out);
}

// round 7
// speedup vs baseline: 2.8431x; 2.8431x over previous
#include <cuda_runtime.h>
#include <cstdint>

// Problem constants
#define BSZ     4
#define SEQ     2048
#define DIMSZ   512
#define HEADS   8
#define HD      64
#define M_TOT   (BSZ * SEQ)   // 8192
#define NEGV    (-1000000.0f)

// Scratch (device globals: allocation rules forbid cudaMalloc)
__device__ float g_Q[M_TOT * DIMSZ];
__device__ float g_K[M_TOT * DIMSZ];
__device__ float g_V[M_TOT * DIMSZ];
__device__ float g_A[M_TOT * DIMSZ];

// ===========================================================================
// Helpers: compute_103-safe PTX only (mma.sync / ldmatrix / cvt.rna.tf32)
// ===========================================================================
__device__ __forceinline__ uint32_t smem_u32(const void* p) {
    uint32_t a;
    asm("{ .reg .u64 t; cvta.to.shared.u64 t, %1; cvt.u32.u64 %0, t; }"
        : "=r"(a) : "l"(p));
    return a;
}

__device__ __forceinline__ uint32_t f2tf(float f) {
    uint32_t u;
    asm("cvt.rna.tf32.f32 %0, %1;" : "=r"(u) : "f"(f));
    return u;
}

__device__ __forceinline__ uint4 cvt4(float4 v) {
    uint4 t;
    t.x = f2tf(v.x); t.y = f2tf(v.y); t.z = f2tf(v.z); t.w = f2tf(v.w);
    return t;
}

__device__ __forceinline__ void ldsm4(uint32_t& r0, uint32_t& r1,
                                      uint32_t& r2, uint32_t& r3,
                                      uint32_t addr) {
    asm volatile("ldmatrix.sync.aligned.m8n8.x4.shared.b16 {%0,%1,%2,%3}, [%4];"
                 : "=r"(r0), "=r"(r1), "=r"(r2), "=r"(r3) : "r"(addr));
}

// D (fp32) += A(tf32 row-major m16 x k8) * B(tf32 col-major k8 x n8)
__device__ __forceinline__ void mma_tf32(float* d, const uint32_t* a,
                                         uint32_t b0, uint32_t b1) {
    asm volatile(
        "mma.sync.aligned.m16n8k8.row.col.f32.tf32.tf32.f32 "
        "{%0,%1,%2,%3}, {%4,%5,%6,%7}, {%8,%9}, {%0,%1,%2,%3};"
        : "+f"(d[0]), "+f"(d[1]), "+f"(d[2]), "+f"(d[3])
        : "r"(a[0]), "r"(a[1]), "r"(a[2]), "r"(a[3]), "r"(b0), "r"(b1));
}

// ===========================================================================
// GEMM:  D[M,512] = A[M,512] * W[512,512]^T   (tf32 mma, fp32 acc)
// CTA tile 128(m) x 64(n), 256 threads, warp tile 32x32, K-chunks of 32.
// SMEM rows = 32 floats (128B, 8 x 16B chunks), xor-swizzled, double-buffered.
// ===========================================================================
#define G_STAGE 24576      // A tile 16KB + W tile 8KB
#define G_SMEM  (2 * G_STAGE)

__global__ __launch_bounds__(256, 2)
void gemm_tc(const float* __restrict__ A, const float* __restrict__ W,
             float* __restrict__ D)
{
    extern __shared__ char sm[];
    const uint32_t sb = smem_u32(sm);
    const int tid = threadIdx.x;
    const int l   = tid & 31;
    const int wid = tid >> 5;
    const int wm  = wid & 3;        // 4 warps along M
    const int wn  = wid >> 2;       // 2 warps along N
    const int rowBase = blockIdx.y * 128;
    const int colBase = blockIdx.x * 64;

    float4 pa[4], pw[2];

    // prefetch chunk c into regs
    auto prefetch = [&](int c) {
#pragma unroll
        for (int i = 0; i < 4; i++) {
            int idx = tid + i * 256;           // 0..1023
            int r = idx >> 3, cc = idx & 7;
            pa[i] = *(const float4*)&A[(size_t)(rowBase + r) * DIMSZ + c * 32 + cc * 4];
        }
#pragma unroll
        for (int i = 0; i < 2; i++) {
            int idx = tid + i * 256;           // 0..511
            int r = idx >> 3, cc = idx & 7;
            pw[i] = *(const float4*)&W[(size_t)(colBase + r) * DIMSZ + c * 32 + cc * 4];
        }
    };
    // store regs into buffer (tf32-converted, swizzled)
    auto stage = [&](int buf) {
        char* base = sm + buf * G_STAGE;
#pragma unroll
        for (int i = 0; i < 4; i++) {
            int idx = tid + i * 256;
            int r = idx >> 3, cc = idx & 7;
            *(uint4*)(base + r * 128 + ((cc ^ (r & 7)) << 4)) = cvt4(pa[i]);
        }
#pragma unroll
        for (int i = 0; i < 2; i++) {
            int idx = tid + i * 256;
            int r = idx >> 3, cc = idx & 7;
            *(uint4*)(base + 16384 + r * 128 + ((cc ^ (r & 7)) << 4)) = cvt4(pw[i]);
        }
    };

    float acc[2][4][4];
#pragma unroll
    for (int im = 0; im < 2; im++)
#pragma unroll
        for (int j = 0; j < 4; j++)
#pragma unroll
            for (int q = 0; q < 4; q++) acc[im][j][q] = 0.f;

    prefetch(0);
    stage(0);

    for (int c = 0; c < 16; ++c) {
        __syncthreads();
        if (c < 15) prefetch(c + 1);
        const uint32_t abase = sb + (c & 1) * G_STAGE;
        const uint32_t wbase = abase + 16384;
#pragma unroll
        for (int s = 0; s < 4; ++s) {
            uint32_t a[2][4];
#pragma unroll
            for (int im = 0; im < 2; im++) {
                int r = 32 * wm + 16 * im + (l & 7) + (((l >> 3) & 1) << 3);
                int cc = (2 * s + (l >> 4)) ^ (r & 7);
                ldsm4(a[im][0], a[im][1], a[im][2], a[im][3],
                      abase + r * 128 + (cc << 4));
            }
            uint32_t b[4][2];
#pragma unroll
            for (int p = 0; p < 2; p++) {
                int r = 32 * wn + 16 * p + (l & 7) + ((l >> 4) << 3);
                int cc = (2 * s + ((l >> 3) & 1)) ^ (r & 7);
                ldsm4(b[2 * p][0], b[2 * p][1], b[2 * p + 1][0], b[2 * p + 1][1],
                      wbase + r * 128 + (cc << 4));
            }
#pragma unroll
            for (int im = 0; im < 2; im++)
#pragma unroll
                for (int j = 0; j < 4; j++)
                    mma_tf32(acc[im][j], a[im], b[j][0], b[j][1]);
        }
        if (c < 15) stage((c + 1) & 1);
    }

    // epilogue
#pragma unroll
    for (int im = 0; im < 2; im++) {
        int r0 = rowBase + 32 * wm + 16 * im + (l >> 2);
#pragma unroll
        for (int j = 0; j < 4; j++) {
            int col = colBase + 32 * wn + 8 * j + 2 * (l & 3);
            *(float2*)&D[(size_t)r0 * DIMSZ + col] =
                make_float2(acc[im][j][0], acc[im][j][1]);
            *(float2*)&D[(size_t)(r0 + 8) * DIMSZ + col] =
                make_float2(acc[im][j][2], acc[im][j][3]);
        }
    }
}

// ===========================================================================
// Fused flash-attention with tf32 mma.sync.
// CTA: 128 q-rows of one (b,h); 8 warps; warp owns 16 q-rows.
// KV tiles of 64.  SMEM rows = 64 floats (256B, 16 chunks), xor-swizzled.
//   Qs[128][64]  (q, d)    pre-scaled by 1/8, tf32
//   Ks[64][64]   (key, d)  tf32
//   Vt[64][64]   (d, key)  tf32 (transposed during staging)
//   Ps[128][64]  (q, key)  tf32
// ===========================================================================
#define AT_QS   0
#define AT_KS   32768
#define AT_VT   49152
#define AT_PS   65536
#define AT_MSK  98304
#define AT_SMEM (98304 + 256)

__global__ __launch_bounds__(256, 2)
void attn_tc(const float* __restrict__ Q, const float* __restrict__ K,
             const float* __restrict__ V, const int* __restrict__ mask,
             float* __restrict__ Aout)
{
    extern __shared__ char sm[];
    const uint32_t sb = smem_u32(sm);
    int* msk = (int*)(sm + AT_MSK);

    const int tid = threadIdx.x;
    const int l   = tid & 31;
    const int w   = tid >> 5;       // warp id: rows 16*w
    const int b   = blockIdx.z;
    const int h   = blockIdx.y;
    const int qb  = blockIdx.x * 128;

    const float* Qb = Q + ((size_t)b * SEQ) * DIMSZ + h * HD;
    const float* Kb = K + ((size_t)b * SEQ) * DIMSZ + h * HD;
    const float* Vb = V + ((size_t)b * SEQ) * DIMSZ + h * HD;
    const int*   mb = mask + b * SEQ;

    // Load Q tile once: (q,d), scaled 1/8, tf32, swizzled
#pragma unroll
    for (int i = 0; i < 8; i++) {
        int idx = tid + i * 256;      // 0..2047
        int r = idx >> 4, cc = idx & 15;
        float4 v = *(const float4*)&Qb[(size_t)(qb + r) * DIMSZ + cc * 4];
        v.x *= 0.125f; v.y *= 0.125f; v.z *= 0.125f; v.w *= 0.125f;
        *(uint4*)(sm + AT_QS + r * 256 + ((cc ^ (r & 7)) << 4)) = cvt4(v);
    }

    float O[8][4];
    float m0 = -1e30f, m1 = -1e30f, l0 = 0.f, l1 = 0.f;
#pragma unroll
    for (int j = 0; j < 8; j++)
#pragma unroll
        for (int q = 0; q < 4; q++) O[j][q] = 0.f;

    for (int k0 = 0; k0 < SEQ; k0 += 64) {
        __syncthreads();   // prev tile's PV reads of Ks/Vt complete
        // stage K (natural) and V (transposed)
#pragma unroll
        for (int i = 0; i < 4; i++) {
            int idx = tid + i * 256;   // 0..1023
            int key = idx >> 4, cc = idx & 15;
            float4 kv = *(const float4*)&Kb[(size_t)(k0 + key) * DIMSZ + cc * 4];
            *(uint4*)(sm + AT_KS + key * 256 + ((cc ^ (key & 7)) << 4)) = cvt4(kv);
            float4 vv = *(const float4*)&Vb[(size_t)(k0 + key) * DIMSZ + cc * 4];
            int d0 = cc * 4;
            int kc = key >> 2, ko = (key & 3) * 4;
            *(uint32_t*)(sm + AT_VT + (d0+0) * 256 + ((kc ^ ((d0+0) & 7)) << 4) + ko) = f2tf(vv.x);
            *(uint32_t*)(sm + AT_VT + (d0+1) * 256 + ((kc ^ ((d0+1) & 7)) << 4) + ko) = f2tf(vv.y);
            *(uint32_t*)(sm + AT_VT + (d0+2) * 256 + ((kc ^ ((d0+2) & 7)) << 4) + ko) = f2tf(vv.z);
            *(uint32_t*)(sm + AT_VT + (d0+3) * 256 + ((kc ^ ((d0+3) & 7)) << 4) + ko) = f2tf(vv.w);
        }
        if (tid < 64) msk[tid] = mb[k0 + tid];
        __syncthreads();

        // ---- S = Qs * Ks^T : warp rows 16w, 8 key-atoms, 8 d-steps ----
        float S[8][4];
#pragma unroll
        for (int j = 0; j < 8; j++)
#pragma unroll
            for (int q = 0; q < 4; q++) S[j][q] = 0.f;

#pragma unroll
        for (int s = 0; s < 8; ++s) {
            uint32_t a[4];
            {
                int r = 16 * w + (l & 7) + (((l >> 3) & 1) << 3);
                int cc = (2 * s + (l >> 4)) ^ (r & 7);
                ldsm4(a[0], a[1], a[2], a[3], sb + AT_QS + r * 256 + (cc << 4));
            }
            uint32_t bq[8][2];
#pragma unroll
            for (int p = 0; p < 4; p++) {
                int r = 16 * p + (l & 7) + ((l >> 4) << 3);
                int cc = (2 * s + ((l >> 3) & 1)) ^ (r & 7);
                ldsm4(bq[2*p][0], bq[2*p][1], bq[2*p+1][0], bq[2*p+1][1],
                      sb + AT_KS + r * 256 + (cc << 4));
            }
#pragma unroll
            for (int j = 0; j < 8; j++)
                mma_tf32(S[j], a, bq[j][0], bq[j][1]);
        }

        // ---- mask (Q pre-scaled, so S already /8) ----
#pragma unroll
        for (int j = 0; j < 8; j++) {
            int kA = 8 * j + 2 * (l & 3);
            int mA = msk[kA], mB = msk[kA + 1];
            S[j][0] = mA ? S[j][0] : NEGV;
            S[j][1] = mB ? S[j][1] : NEGV;
            S[j][2] = mA ? S[j][2] : NEGV;
            S[j][3] = mB ? S[j][3] : NEGV;
        }

        // ---- online softmax (rows l/4 and l/4+8; quad = lanes sharing l/4) ----
        float mx0 = -1e30f, mx1 = -1e30f;
#pragma unroll
        for (int j = 0; j < 8; j++) {
            mx0 = fmaxf(mx0, fmaxf(S[j][0], S[j][1]));
            mx1 = fmaxf(mx1, fmaxf(S[j][2], S[j][3]));
        }
        mx0 = fmaxf(mx0, __shfl_xor_sync(0xffffffffu, mx0, 1));
        mx0 = fmaxf(mx0, __shfl_xor_sync(0xffffffffu, mx0, 2));
        mx1 = fmaxf(mx1, __shfl_xor_sync(0xffffffffu, mx1, 1));
        mx1 = fmaxf(mx1, __shfl_xor_sync(0xffffffffu, mx1, 2));

        float mn0 = fmaxf(m0, mx0), mn1 = fmaxf(m1, mx1);
        float cr0 = __expf(m0 - mn0), cr1 = __expf(m1 - mn1);
        m0 = mn0; m1 = mn1;

        float rs0 = 0.f, rs1 = 0.f;
        const int qr  = 16 * w + (l >> 2);
        const int kAc = 2 * (l & 3);          // key offset within atom
#pragma unroll
        for (int j = 0; j < 8; j++) {
            float p0 = __expf(S[j][0] - mn0);
            float p1 = __expf(S[j][1] - mn0);
            float p2 = __expf(S[j][2] - mn1);
            float p3 = __expf(S[j][3] - mn1);
            rs0 += p0 + p1; rs1 += p2 + p3;
            // store P (tf32) to Ps[q][key]
            int kA = 8 * j + kAc;
            int kc = kA >> 2, ko = (kA & 3) * 4;
            *(uint2*)(sm + AT_PS + qr * 256 + ((kc ^ (qr & 7)) << 4) + ko) =
                make_uint2(f2tf(p0), f2tf(p1));
            int qr8 = qr + 8;
            *(uint2*)(sm + AT_PS + qr8 * 256 + ((kc ^ (qr8 & 7)) << 4) + ko) =
                make_uint2(f2tf(p2), f2tf(p3));
        }
        rs0 += __shfl_xor_sync(0xffffffffu, rs0, 1);
        rs0 += __shfl_xor_sync(0xffffffffu, rs0, 2);
        rs1 += __shfl_xor_sync(0xffffffffu, rs1, 1);
        rs1 += __shfl_xor_sync(0xffffffffu, rs1, 2);
        l0 = l0 * cr0 + rs0;
        l1 = l1 * cr1 + rs1;

#pragma unroll
        for (int j = 0; j < 8; j++) {
            O[j][0] *= cr0; O[j][1] *= cr0;
            O[j][2] *= cr1; O[j][3] *= cr1;
        }
        __syncwarp();   // Ps rows are warp-private; order stores before ldmatrix

        // ---- O += P * V : 8 d-atoms, 8 key-steps ----
#pragma unroll
        for (int s = 0; s < 8; ++s) {
            uint32_t a[4];
            {
                int r = 16 * w + (l & 7) + (((l >> 3) & 1) << 3);
                int cc = (2 * s + (l >> 4)) ^ (r & 7);
                ldsm4(a[0], a[1], a[2], a[3], sb + AT_PS + r * 256 + (cc << 4));
            }
            uint32_t bv[8][2];
#pragma unroll
            for (int p = 0; p < 4; p++) {
                int r = 16 * p + (l & 7) + ((l >> 4) << 3);   // r = d row
                int cc = (2 * s + ((l >> 3) & 1)) ^ (r & 7);
                ldsm4(bv[2*p][0], bv[2*p][1], bv[2*p+1][0], bv[2*p+1][1],
                      sb + AT_VT + r * 256 + (cc << 4));
            }
#pragma unroll
            for (int j = 0; j < 8; j++)
                mma_tf32(O[j], a, bv[j][0], bv[j][1]);
        }
    }

    // ---- epilogue: normalize, write head-merged fp32 ----
    const float inv0 = 1.0f / l0, inv1 = 1.0f / l1;
    const int qr = qb + 16 * w + (l >> 2);
#pragma unroll
    for (int j = 0; j < 8; j++) {
        int col = h * HD + 8 * j + 2 * (l & 3);
        *(float2*)&Aout[((size_t)b * SEQ + qr) * DIMSZ + col] =
            make_float2(O[j][0] * inv0, O[j][1] * inv0);
        *(float2*)&Aout[((size_t)b * SEQ + qr + 8) * DIMSZ + col] =
            make_float2(O[j][2] * inv1, O[j][3] * inv1);
    }
}

// ---------------------------------------------------------------------------
extern "C" void kernel_launch(void* const* d_in, const int* in_sizes, int n_in,
                              void* d_out, int out_size)
{
    (void)in_sizes; (void)n_in; (void)out_size;
    const float* x    = (const float*)d_in[0];
    const float* Wq   = (const float*)d_in[1];
    const float* Wk   = (const float*)d_in[2];
    const float* Wv   = (const float*)d_in[3];
    const float* Wo   = (const float*)d_in[4];
    const int*   mask = (const int*)d_in[5];
    float*       out  = (float*)d_out;

    float *Qp = nullptr, *Kp = nullptr, *Vp = nullptr, *Ap = nullptr;
    cudaGetSymbolAddress((void**)&Qp, g_Q);
    cudaGetSymbolAddress((void**)&Kp, g_K);
    cudaGetSymbolAddress((void**)&Vp, g_V);
    cudaGetSymbolAddress((void**)&Ap, g_A);

    cudaFuncSetAttribute(gemm_tc,
                         cudaFuncAttributeMaxDynamicSharedMemorySize, G_SMEM);
    cudaFuncSetAttribute(attn_tc,
                         cudaFuncAttributeMaxDynamicSharedMemorySize, AT_SMEM);

    dim3 ggrid(DIMSZ / 64, M_TOT / 128);   // (8, 64)
    gemm_tc<<<ggrid, 256, G_SMEM>>>(x, Wq, Qp);
    gemm_tc<<<ggrid, 256, G_SMEM>>>(x, Wk, Kp);
    gemm_tc<<<ggrid, 256, G_SMEM>>>(x, Wv, Vp);

    attn_tc<<<dim3(SEQ / 128, HEADS, BSZ), 256, AT_SMEM>>>(Qp, Kp, Vp, mask, Ap);

    gemm_tc<<<ggrid, 256, G_SMEM>>>(Ap, Wo, out);
}